// round 1
// baseline (speedup 1.0000x reference)
#include <cuda_runtime.h>

#define B 4
#define L 1024
#define D 768
#define H 12
#define NE 42
#define M 8
#define NE2 (NE*NE)   /* 1764 */
#define LC 16

// Scratch (device globals; no allocation in kernel_launch)
__device__ __align__(16) float g_ent_att[B*H*NE*L];   // 8.26 MB  [B][H][NE][L]
__device__ __align__(16) float g_ht[(size_t)B*NE2*L]; // 28.9 MB  [B][NE*NE][L] (unnormalized, /H included)
__device__ __align__(16) float g_inv[B*NE2];          // 1/(rowsum + 1e-5)

// ---------------------------------------------------------------------------
// K1: ent_att[b,h,s,l] = (1/cnt) * sum_m valid * attention[b,h,idx,l]
// grid = B*H*NE blocks, 256 threads
// ---------------------------------------------------------------------------
__global__ void k_ent_att(const float* __restrict__ att,
                          const int* __restrict__ midx,
                          const int* __restrict__ mmask) {
    int id = blockIdx.x;            // (b*H + h)*NE + s
    int s  = id % NE;
    int bh = id / NE;
    int h  = bh % H;
    int b  = bh / H;

    int rows[M];
    int nv = 0;
#pragma unroll
    for (int m = 0; m < M; m++) {
        int base = (b*NE + s)*M + m;
        int idx = midx[base] + 1;                       // OFFSET = 1
        bool v = (mmask[base] > 0) && (idx < L);
        rows[m] = v ? idx : -1;
        nv += v ? 1 : 0;
    }
    float inv = 1.0f / (float)(nv < 1 ? 1 : nv);

    const float* abh = att + (size_t)(b*H + h) * L * L;
    float* outp = g_ent_att + (size_t)id * L;

    for (int l = threadIdx.x; l < L; l += blockDim.x) {
        float acc = 0.0f;
#pragma unroll
        for (int m = 0; m < M; m++)
            if (rows[m] >= 0) acc += abh[(size_t)rows[m]*L + l];
        outp[l] = acc * inv;
    }
}

// ---------------------------------------------------------------------------
// K2: ht[b,s,t,l] = (1/H) * sum_h ent_att[b,h,s,l]*ent_att[b,h,t,l]
// block per (b, l-chunk of 16). 252 active threads: each owns one s and 7 t's.
// ---------------------------------------------------------------------------
__global__ void k_ht() {
    __shared__ float Es[H*NE*(LC+1)];   // padded stride 17 -> conflict-free
    int nchunk = L / LC;
    int b  = blockIdx.x / nchunk;
    int l0 = (blockIdx.x % nchunk) * LC;

    for (int i = threadIdx.x; i < H*NE*LC; i += blockDim.x) {
        int lc = i % LC;
        int hs = i / LC;      // h*NE + s
        Es[hs*(LC+1) + lc] = g_ent_att[(size_t)(b*H*NE + hs)*L + l0 + lc];
    }
    __syncthreads();

    int tid = threadIdx.x;
    if (tid >= 252) return;
    int s  = tid / 6;
    int t0 = (tid % 6) * 7;
    const float invH = 1.0f / (float)H;

    for (int l = 0; l < LC; l++) {
        float es[H];
#pragma unroll
        for (int h = 0; h < H; h++) es[h] = Es[(h*NE + s)*(LC+1) + l];
#pragma unroll
        for (int tt = 0; tt < 7; tt++) {
            int t = t0 + tt;
            float acc = 0.0f;
#pragma unroll
            for (int h = 0; h < H; h++) acc += es[h] * Es[(h*NE + t)*(LC+1) + l];
            g_ht[((size_t)(b*NE2 + s*NE + t))*L + l0 + l] = acc * invH;
        }
    }
}

// ---------------------------------------------------------------------------
// K2b: g_inv[row] = 1/(sum_l ht[row,l] + 1e-5). grid = B*NE2 blocks.
// ---------------------------------------------------------------------------
__global__ void k_rowsum() {
    int row = blockIdx.x;
    const float* p = g_ht + (size_t)row * L;
    float acc = 0.0f;
    for (int l = threadIdx.x; l < L; l += 256) acc += p[l];
    __shared__ float red[256];
    red[threadIdx.x] = acc;
    __syncthreads();
    for (int s = 128; s > 0; s >>= 1) {
        if (threadIdx.x < s) red[threadIdx.x] += red[threadIdx.x + s];
        __syncthreads();
    }
    if (threadIdx.x == 0) g_inv[row] = 1.0f / (red[0] + 1e-5f);
}

// ---------------------------------------------------------------------------
// K3: feature[b,st,d] = g_inv[b,st] * sum_l ht[b,st,l] * seq[b,l,d]
// Classic 128x128x16 fp32 SGEMM, 256 threads, 8x8 per-thread tile.
// grid = (ceil(1764/128)=14, 768/128=6, B)
// ---------------------------------------------------------------------------
#define BM 128
#define BN 128
#define BK 16

__global__ __launch_bounds__(256) void k_gemm(const float* __restrict__ seq,
                                              float* __restrict__ outp) {
    __shared__ float As[BK][BM];
    __shared__ float Bs[BK][BN];

    int b    = blockIdx.z;
    int row0 = blockIdx.x * BM;
    int col0 = blockIdx.y * BN;

    const float* Wb = g_ht + (size_t)b * NE2 * L;
    const float* Sb = seq  + (size_t)b * L * D;

    int tid = threadIdx.x;
    int tx = tid % 16, ty = tid / 16;

    float acc[8][8];
#pragma unroll
    for (int i = 0; i < 8; i++)
#pragma unroll
        for (int j = 0; j < 8; j++) acc[i][j] = 0.0f;

    for (int k0 = 0; k0 < L; k0 += BK) {
        // A tile: 128 rows x 16 k (transposed store)
#pragma unroll
        for (int i = 0; i < 2; i++) {
            int slot = tid + 256*i;         // 512 float4 slots
            int r  = slot >> 2;             // 0..127
            int kk = (slot & 3) * 4;        // 0,4,8,12
            float4 v = make_float4(0.f, 0.f, 0.f, 0.f);
            int grow = row0 + r;
            if (grow < NE2) v = *(const float4*)&Wb[(size_t)grow*L + k0 + kk];
            As[kk+0][r] = v.x; As[kk+1][r] = v.y;
            As[kk+2][r] = v.z; As[kk+3][r] = v.w;
        }
        // B tile: 16 k x 128 cols
#pragma unroll
        for (int i = 0; i < 2; i++) {
            int slot = tid + 256*i;
            int r  = slot >> 5;             // 0..15
            int cc = (slot & 31) * 4;       // 0..124
            *(float4*)&Bs[r][cc] = *(const float4*)&Sb[(size_t)(k0 + r)*D + col0 + cc];
        }
        __syncthreads();

#pragma unroll
        for (int k = 0; k < BK; k++) {
            float a[8], bb[8];
            *(float4*)&a[0]  = *(const float4*)&As[k][ty*8];
            *(float4*)&a[4]  = *(const float4*)&As[k][ty*8 + 4];
            *(float4*)&bb[0] = *(const float4*)&Bs[k][tx*8];
            *(float4*)&bb[4] = *(const float4*)&Bs[k][tx*8 + 4];
#pragma unroll
            for (int i = 0; i < 8; i++)
#pragma unroll
                for (int j = 0; j < 8; j++)
                    acc[i][j] += a[i] * bb[j];
        }
        __syncthreads();
    }

#pragma unroll
    for (int i = 0; i < 8; i++) {
        int grow = row0 + ty*8 + i;
        if (grow >= NE2) continue;
        float scale = g_inv[b*NE2 + grow];
        float* op = outp + ((size_t)(b*NE2 + grow))*D + col0 + tx*8;
#pragma unroll
        for (int j = 0; j < 8; j += 4) {
            float4 v;
            v.x = acc[i][j+0] * scale;
            v.y = acc[i][j+1] * scale;
            v.z = acc[i][j+2] * scale;
            v.w = acc[i][j+3] * scale;
            *(float4*)&op[j] = v;
        }
    }
}

// ---------------------------------------------------------------------------
extern "C" void kernel_launch(void* const* d_in, const int* in_sizes, int n_in,
                              void* d_out, int out_size) {
    const float* seq   = (const float*)d_in[0];  // [B,L,D]
    const float* att   = (const float*)d_in[1];  // [B,H,L,L]
    const int*   midx  = (const int*)d_in[2];    // [B,NE,M]
    const int*   mmask = (const int*)d_in[3];    // [B,NE,M]
    float* outp = (float*)d_out;                 // [B,NE,NE,D]

    k_ent_att<<<B*H*NE, 256>>>(att, midx, mmask);
    k_ht<<<B*(L/LC), 256>>>();
    k_rowsum<<<B*NE2, 256>>>();
    dim3 grid((NE2 + BM - 1)/BM, D/BN, B);
    k_gemm<<<grid, 256>>>(seq, outp);
}

// round 3
// speedup vs baseline: 1.9799x; 1.9799x over previous
#include <cuda_runtime.h>
#include <cuda_bf16.h>
#include <cstdint>

#define B 4
#define L 1024
#define D 768
#define H 12
#define NE 42
#define M 8
#define NE2 (NE*NE)   /* 1764 */
#define LC 16

// Scratch
__device__ __align__(16) float g_ent_att[B*H*NE*L];   // [B][H][NE][L]
__device__ __align__(16) float g_ht[(size_t)B*NE2*L]; // [B][NE*NE][L]  (includes /H)
__device__ float g_rowsum[B*NE2];

__device__ __forceinline__ uint32_t smem_u32(const void* p) {
    uint32_t a;
    asm("{ .reg .u64 t; cvta.to.shared.u64 t, %1; cvt.u32.u64 %0, t; }" : "=r"(a) : "l"(p));
    return a;
}

// ---------------------------------------------------------------------------
// K0: zero rowsum accumulator
// ---------------------------------------------------------------------------
__global__ void k_zero() {
    int i = blockIdx.x * 256 + threadIdx.x;
    if (i < B*NE2) g_rowsum[i] = 0.0f;
}

// ---------------------------------------------------------------------------
// K1: ent_att[b,h,s,l] = (1/cnt) * sum_m valid * attention[b,h,idx,l]
// ---------------------------------------------------------------------------
__global__ void k_ent_att(const float* __restrict__ att,
                          const int* __restrict__ midx,
                          const int* __restrict__ mmask) {
    int id = blockIdx.x;
    int s  = id % NE;
    int bh = id / NE;
    int b  = bh / H;

    int rows[M];
    int nv = 0;
#pragma unroll
    for (int m = 0; m < M; m++) {
        int base = (b*NE + s)*M + m;
        int idx = midx[base] + 1;
        bool v = (mmask[base] > 0) && (idx < L);
        rows[m] = v ? idx : -1;
        nv += v ? 1 : 0;
    }
    float inv = 1.0f / (float)(nv < 1 ? 1 : nv);

    const float* abh = att + (size_t)bh * L * L;
    float* outp = g_ent_att + (size_t)id * L;

    for (int l = threadIdx.x; l < L; l += blockDim.x) {
        float acc = 0.0f;
#pragma unroll
        for (int m = 0; m < M; m++)
            if (rows[m] >= 0) acc += abh[(size_t)rows[m]*L + l];
        outp[l] = acc * inv;
    }
}

// ---------------------------------------------------------------------------
// K2: ht + fused rowsum
// ---------------------------------------------------------------------------
__global__ void k_ht() {
    __shared__ float Es[H*NE*(LC+1)];
    int nchunk = L / LC;
    int b  = blockIdx.x / nchunk;
    int l0 = (blockIdx.x % nchunk) * LC;

    for (int i = threadIdx.x; i < H*NE*LC; i += blockDim.x) {
        int lc = i % LC;
        int hs = i / LC;
        Es[hs*(LC+1) + lc] = g_ent_att[(size_t)(b*H*NE + hs)*L + l0 + lc];
    }
    __syncthreads();

    int tid = threadIdx.x;
    if (tid >= 252) return;
    int s  = tid / 6;
    int t0 = (tid % 6) * 7;
    const float invH = 1.0f / (float)H;

    float rs[7];
#pragma unroll
    for (int tt = 0; tt < 7; tt++) rs[tt] = 0.0f;

    for (int l = 0; l < LC; l++) {
        float es[H];
#pragma unroll
        for (int h = 0; h < H; h++) es[h] = Es[(h*NE + s)*(LC+1) + l];
#pragma unroll
        for (int tt = 0; tt < 7; tt++) {
            int t = t0 + tt;
            float acc = 0.0f;
#pragma unroll
            for (int h = 0; h < H; h++) acc += es[h] * Es[(h*NE + t)*(LC+1) + l];
            acc *= invH;
            g_ht[((size_t)(b*NE2 + s*NE + t))*L + l0 + l] = acc;
            rs[tt] += acc;
        }
    }
#pragma unroll
    for (int tt = 0; tt < 7; tt++)
        atomicAdd(&g_rowsum[b*NE2 + s*NE + t0 + tt], rs[tt]);
}

// ---------------------------------------------------------------------------
// K3: mma.sync bf16 3-split GEMM (HMMA path — tcgen05 PTX rejected by
// harness's non-'a' ptxas target).
// out[b,row,d] = (1/(rowsum+1e-5)) * sum_l ht[b,row,l] * seq[b,l,d]
// CTA 128x128, BK=32, 8 warps (4m x 2n), warp tile 32x64.
// ---------------------------------------------------------------------------
#define BM 128
#define BN 128
#define BK 32

// SMEM byte strides chosen for conflict-free ldmatrix (8 rows -> 8 distinct
// 16B banks): A stride 80B (80*i mod 128 all distinct), B stride 272B.
#define A_STRIDE 80
#define B_STRIDE 272
#define SM_AH 0
#define SM_AL (SM_AH + BM*A_STRIDE)           /* 10240 */
#define SM_BH (SM_AL + BM*A_STRIDE)           /* 20480 */
#define SM_BL (SM_BH + BK*B_STRIDE)           /* 29184 */
#define SM_TOT (SM_BL + BK*B_STRIDE)          /* 37888 */

__device__ __forceinline__ void ldsm_x4(uint32_t* r, uint32_t addr) {
    asm volatile("ldmatrix.sync.aligned.m8n8.x4.shared.b16 {%0,%1,%2,%3}, [%4];"
                 : "=r"(r[0]), "=r"(r[1]), "=r"(r[2]), "=r"(r[3]) : "r"(addr));
}
__device__ __forceinline__ void ldsm_x4_t(uint32_t* r, uint32_t addr) {
    asm volatile("ldmatrix.sync.aligned.m8n8.x4.trans.shared.b16 {%0,%1,%2,%3}, [%4];"
                 : "=r"(r[0]), "=r"(r[1]), "=r"(r[2]), "=r"(r[3]) : "r"(addr));
}
__device__ __forceinline__ void mma_bf16(float* c, const uint32_t* a, const uint32_t* b) {
    asm volatile(
        "mma.sync.aligned.m16n8k16.row.col.f32.bf16.bf16.f32 "
        "{%0,%1,%2,%3}, {%4,%5,%6,%7}, {%8,%9}, {%0,%1,%2,%3};"
        : "+f"(c[0]), "+f"(c[1]), "+f"(c[2]), "+f"(c[3])
        : "r"(a[0]), "r"(a[1]), "r"(a[2]), "r"(a[3]), "r"(b[0]), "r"(b[1]));
}

__device__ __forceinline__ uint2 split_pack(float4 v, uint2& lo) {
    __nv_bfloat162 h0 = __floats2bfloat162_rn(v.x, v.y);
    __nv_bfloat162 h1 = __floats2bfloat162_rn(v.z, v.w);
    __nv_bfloat162 e0 = __floats2bfloat162_rn(v.x - __bfloat162float(h0.x),
                                              v.y - __bfloat162float(h0.y));
    __nv_bfloat162 e1 = __floats2bfloat162_rn(v.z - __bfloat162float(h1.x),
                                              v.w - __bfloat162float(h1.y));
    uint2 hi;
    hi.x = *(uint32_t*)&h0; hi.y = *(uint32_t*)&h1;
    lo.x = *(uint32_t*)&e0; lo.y = *(uint32_t*)&e1;
    return hi;
}

__global__ __launch_bounds__(256, 2) void k_gemm(const float* __restrict__ seq,
                                                 float* __restrict__ outp) {
    __shared__ __align__(16) char smem[SM_TOT];
    uint32_t sb = smem_u32(smem);

    int tid  = threadIdx.x;
    int wid  = tid >> 5;
    int lane = tid & 31;

    int b    = blockIdx.z;
    int row0 = blockIdx.x * BM;
    int col0 = blockIdx.y * BN;

    const float* Wb = g_ht + (size_t)b * NE2 * L;
    const float* Sb = seq  + (size_t)b * L * D;

    int wm = (wid & 3) * 32;   // warp m offset in tile
    int wn = (wid >> 2) * 64;  // warp n offset in tile

    float acc[2][8][4];
#pragma unroll
    for (int i = 0; i < 2; i++)
#pragma unroll
        for (int j = 0; j < 8; j++)
#pragma unroll
            for (int q = 0; q < 4; q++) acc[i][j][q] = 0.0f;

    // ldmatrix addresses (constant across k-tiles modulo k-step offset)
    int lr  = lane & 15;
    int lc8 = (lane >> 4) << 3;
    uint32_t aAddrH0 = sb + SM_AH + (wm + lr) * A_STRIDE + lc8 * 2;
    uint32_t aAddrL0 = sb + SM_AL + (wm + lr) * A_STRIDE + lc8 * 2;
    uint32_t bAddrH0 = sb + SM_BH + lr * B_STRIDE + (wn + lc8) * 2;
    uint32_t bAddrL0 = sb + SM_BL + lr * B_STRIDE + (wn + lc8) * 2;

    for (int kt = 0; kt < L/BK; kt++) {
        int l0 = kt * BK;
        __syncthreads();

        // ---- A tile: 128 rows x 32 l (hi + lo) ----
#pragma unroll
        for (int i = 0; i < 4; i++) {
            int slot = tid + 256*i;          // 1024 float4 slots
            int r = slot >> 3;
            int q = slot & 7;
            float4 v = make_float4(0.f, 0.f, 0.f, 0.f);
            int grow = row0 + r;
            if (grow < NE2) v = *(const float4*)&Wb[(size_t)grow*L + l0 + q*4];
            uint2 lo, hi = split_pack(v, lo);
            *(uint2*)(smem + SM_AH + r*A_STRIDE + q*8) = hi;
            *(uint2*)(smem + SM_AL + r*A_STRIDE + q*8) = lo;
        }
        // ---- B tile: 32 l-rows x 128 d (hi + lo) ----
#pragma unroll
        for (int i = 0; i < 4; i++) {
            int slot = tid + 256*i;
            int l  = slot >> 5;
            int dq = slot & 31;
            float4 v = *(const float4*)&Sb[(size_t)(l0 + l)*D + col0 + dq*4];
            uint2 lo, hi = split_pack(v, lo);
            *(uint2*)(smem + SM_BH + l*B_STRIDE + dq*8) = hi;
            *(uint2*)(smem + SM_BL + l*B_STRIDE + dq*8) = lo;
        }
        __syncthreads();

        // ---- compute: 2 k16 steps ----
#pragma unroll
        for (int ks = 0; ks < 2; ks++) {
            int kb = ks * 32;    // byte offset of k16 step (16 bf16 = 32B)
            uint32_t ah[2][4], al[2][4];
            ldsm_x4(ah[0], aAddrH0 + kb);
            ldsm_x4(ah[1], aAddrH0 + 16*A_STRIDE + kb);
            ldsm_x4(al[0], aAddrL0 + kb);
            ldsm_x4(al[1], aAddrL0 + 16*A_STRIDE + kb);

            uint32_t bh[4][4], bl[4][4];
#pragma unroll
            for (int nb = 0; nb < 4; nb++) {
                ldsm_x4_t(bh[nb], bAddrH0 + ks*16*B_STRIDE + nb*32);
                ldsm_x4_t(bl[nb], bAddrL0 + ks*16*B_STRIDE + nb*32);
            }
#pragma unroll
            for (int mi = 0; mi < 2; mi++) {
#pragma unroll
                for (int nj = 0; nj < 8; nj++) {
                    const uint32_t* bfh = &bh[nj>>1][(nj&1)*2];
                    const uint32_t* bfl = &bl[nj>>1][(nj&1)*2];
                    mma_bf16(acc[mi][nj], ah[mi], bfh);
                    mma_bf16(acc[mi][nj], ah[mi], bfl);
                    mma_bf16(acc[mi][nj], al[mi], bfh);
                }
            }
        }
    }

    // ---- Epilogue: scale by 1/(rowsum+eps), guarded store ----
    int g = lane >> 2;          // 0..7
    int t = lane & 3;           // 0..3
#pragma unroll
    for (int mi = 0; mi < 2; mi++) {
#pragma unroll
        for (int half = 0; half < 2; half++) {
            int grow = row0 + wm + mi*16 + g + half*8;
            if (grow >= NE2) continue;
            float scale = 1.0f / (g_rowsum[b*NE2 + grow] + 1e-5f);
            float* op = outp + ((size_t)(b*NE2 + grow))*D + col0 + wn;
#pragma unroll
            for (int nj = 0; nj < 8; nj++) {
                float2 v;
                v.x = acc[mi][nj][half*2+0] * scale;
                v.y = acc[mi][nj][half*2+1] * scale;
                *(float2*)&op[nj*8 + t*2] = v;
            }
        }
    }
}

// ---------------------------------------------------------------------------
extern "C" void kernel_launch(void* const* d_in, const int* in_sizes, int n_in,
                              void* d_out, int out_size) {
    const float* seq   = (const float*)d_in[0];
    const float* att   = (const float*)d_in[1];
    const int*   midx  = (const int*)d_in[2];
    const int*   mmask = (const int*)d_in[3];
    float* outp = (float*)d_out;

    k_zero<<<(B*NE2 + 255)/256, 256>>>();
    k_ent_att<<<B*H*NE, 256>>>(att, midx, mmask);
    k_ht<<<B*(L/LC), 256>>>();
    dim3 grid((NE2 + BM - 1)/BM, D/BN, B);
    k_gemm<<<grid, 256>>>(seq, outp);
}